// round 14
// baseline (speedup 1.0000x reference)
#include <cuda_runtime.h>
#include <cuda_bf16.h>
#include <cstdint>

// out[b,i,:] = sum_j exp(q_i . k_j) * v_j   (B=4, S=4096, D=64, fp32)
// R14: two independent 256-thread warp-groups per CTA (named barriers,
//      private double-buffered K/V stages) -> desynchronized pipelines.
//      K/V pre-split to bf16 hi/lo globals; cp.async staging; register P.

#define S_LEN 4096
#define B_SZ  4
#define DD    64
#define TQ    128
#define TK    64
#define NTH   512
#define NTILES (S_LEN / TK)

#define PITCH 144               // 64 bf16 + 8B pad
#define KBUF  (TK * PITCH)      // 9216 per hi/lo buffer
#define STAGE (4 * KBUF)        // Khi,Klo,Vhi,Vlo = 36864 per stage
#define GBUF  (2 * STAGE)       // 73728 per group (2 stages)
#define SM_TOTAL (2 * GBUF)     // 147456 B
#define RED_PITCH 72

#define LOG2E 1.4426950408889634f

#define NROWS (B_SZ * S_LEN)
__device__ __align__(16) unsigned char g_khi[NROWS * 128];
__device__ __align__(16) unsigned char g_klo[NROWS * 128];
__device__ __align__(16) unsigned char g_vhi[NROWS * 128];
__device__ __align__(16) unsigned char g_vlo[NROWS * 128];

__device__ __forceinline__ uint32_t smem_u32(const void* p) {
    uint32_t a;
    asm("{ .reg .u64 t; cvta.to.shared.u64 t, %1; cvt.u32.u64 %0, t; }" : "=r"(a) : "l"(p));
    return a;
}
#define LDMX4(r, a) \
    asm volatile("ldmatrix.sync.aligned.m8n8.x4.shared.b16 {%0,%1,%2,%3}, [%4];" \
        : "=r"((r)[0]), "=r"((r)[1]), "=r"((r)[2]), "=r"((r)[3]) : "r"(a))
#define LDMX4T(r, a) \
    asm volatile("ldmatrix.sync.aligned.m8n8.x4.trans.shared.b16 {%0,%1,%2,%3}, [%4];" \
        : "=r"((r)[0]), "=r"((r)[1]), "=r"((r)[2]), "=r"((r)[3]) : "r"(a))
#define MMA(c, av, bv) \
    asm volatile("mma.sync.aligned.m16n8k16.row.col.f32.bf16.bf16.f32 " \
        "{%0,%1,%2,%3}, {%4,%5,%6,%7}, {%8,%9}, {%0,%1,%2,%3};" \
        : "+f"((c)[0]), "+f"((c)[1]), "+f"((c)[2]), "+f"((c)[3]) \
        : "r"((av)[0]), "r"((av)[1]), "r"((av)[2]), "r"((av)[3]), \
          "r"((bv)[0]), "r"((bv)[1]))
#define CP16(dst, src) \
    asm volatile("cp.async.cg.shared.global [%0], [%1], 16;" \
        :: "r"(dst), "l"(src) : "memory")
#define CP_COMMIT() asm volatile("cp.async.commit_group;" ::: "memory")
#define CP_WAIT0()  asm volatile("cp.async.wait_group 0;" ::: "memory")
#define GBAR(id)    asm volatile("bar.sync %0, 256;" :: "r"(id) : "memory")

__device__ __forceinline__ float ex2f(float x) {
    float r;
    asm("ex2.approx.ftz.f32 %0, %1;" : "=f"(r) : "f"(x));
    return r;
}
__device__ __forceinline__ void split_pack(float x, float y, uint32_t& hi, uint32_t& lo) {
    asm("cvt.rn.bf16x2.f32 %0, %1, %2;" : "=r"(hi) : "f"(y), "f"(x));
    float xh = __uint_as_float(hi << 16);
    float yh = __uint_as_float(hi & 0xffff0000u);
    asm("cvt.rn.bf16x2.f32 %0, %1, %2;" : "=r"(lo) : "f"(y - yh), "f"(x - xh));
}

// ---------------- pre-pass: split K,V into bf16 hi/lo ----------------
__global__ void __launch_bounds__(256)
split_kv_kernel(const float* __restrict__ k, const float* __restrict__ v)
{
    const int total = NROWS * DD / 4;
    uint2* khi = (uint2*)g_khi;
    uint2* klo = (uint2*)g_klo;
    uint2* vhi = (uint2*)g_vhi;
    uint2* vlo = (uint2*)g_vlo;
    for (int i = blockIdx.x * blockDim.x + threadIdx.x; i < total;
         i += gridDim.x * blockDim.x) {
        float4 a = ((const float4*)k)[i];
        uint32_t h0, l0, h1, l1;
        split_pack(a.x, a.y, h0, l0);
        split_pack(a.z, a.w, h1, l1);
        khi[i] = make_uint2(h0, h1);
        klo[i] = make_uint2(l0, l1);
        float4 c = ((const float4*)v)[i];
        split_pack(c.x, c.y, h0, l0);
        split_pack(c.z, c.w, h1, l1);
        vhi[i] = make_uint2(h0, h1);
        vlo[i] = make_uint2(l0, l1);
    }
}

// ---------------- main kernel ----------------
__global__ void __launch_bounds__(NTH, 1)
fa_fa14_kernel(const float* __restrict__ q, float* __restrict__ out)
{
    extern __shared__ char smem[];
    const uint32_t sb = smem_u32(smem);
    const int tid  = threadIdx.x;
    const int wid  = tid >> 5;
    const int lane = tid & 31;
    const int gid  = wid >> 3;          // warp-group 0/1 (rows gid*64..+63)
    const int lw   = wid & 7;           // warp within group
    const int m    = lw & 3;            // M-subgroup: rows gid*64 + m*16 ..
    const int gk   = lw >> 2;           // key-split: keys gk*32..+31 of tile
    const int lt   = tid & 255;         // thread id within group
    const int bar  = 1 + gid;
    const int b  = blockIdx.y;
    const int q0 = blockIdx.x * TQ;

    const float* Qg = q + ((size_t)b * S_LEN + q0) * DD;
    float*       Og = out + ((size_t)b * S_LEN + q0) * DD;
    const size_t rowbase = (size_t)b * S_LEN;

    const uint32_t gbase = sb + (uint32_t)(gid * GBUF);
    char* gmem_sm = smem + gid * GBUF;

    // cp.async per-thread: 2 x 16B per buffer (64 rows x 128 B / 256 thr)
    const int crow = lt >> 2;           // 0..63
    const int cj   = (lt & 3) * 32;     // 0,32,64,96
    const uint32_t stBase = gbase + (uint32_t)(crow * PITCH + cj);

    // ---- prologue: stage Q (x log2e) across smem, grab persistent A-frags ----
    {
        #pragma unroll
        for (int i = 0; i < 4; ++i) {
            int f = tid + i * NTH;
            int row = f >> 4, d0 = (f & 15) << 2;
            float4 t = *(const float4*)&Qg[(size_t)row * DD + d0];
            uint32_t h0, l0, h1, l1;
            split_pack(t.x * LOG2E, t.y * LOG2E, h0, l0);
            split_pack(t.z * LOG2E, t.w * LOG2E, h1, l1);
            int off = row * PITCH + d0 * 2;
            *(uint2*)(smem + off)              = make_uint2(h0, h1);
            *(uint2*)(smem + TQ * PITCH + off) = make_uint2(l0, l1);
        }
    }
    __syncthreads();

    uint32_t qhi[4][4], qlo[4][4];
    {
        const uint32_t aQ = sb +
            (uint32_t)((gid * 64 + m * 16 + (lane & 15)) * PITCH + (lane >> 4) * 16);
        #pragma unroll
        for (int ks = 0; ks < 4; ++ks) {
            LDMX4(qhi[ks], aQ + ks * 32);
            LDMX4(qlo[ks], aQ + TQ * PITCH + ks * 32);
        }
    }
    __syncthreads();    // Q smem region free (aliases group0 stages)

    // stage K0,V0 into group's stage 0
    {
        size_t off = (rowbase + crow) * 128 + cj;
        CP16(stBase,              (const char*)g_khi + off);
        CP16(stBase + 16,         (const char*)g_khi + off + 16);
        CP16(stBase + KBUF,       (const char*)g_klo + off);
        CP16(stBase + KBUF + 16,  (const char*)g_klo + off + 16);
        CP16(stBase + 2*KBUF,     (const char*)g_vhi + off);
        CP16(stBase + 2*KBUF + 16,(const char*)g_vhi + off + 16);
        CP16(stBase + 3*KBUF,     (const char*)g_vlo + off);
        CP16(stBase + 3*KBUF + 16,(const char*)g_vlo + off + 16);
        CP_COMMIT();
        CP_WAIT0();
    }
    GBAR(bar);

    // per-lane B-operand bases within a stage (stage offset added at use)
    const uint32_t bK = gbase +
        (uint32_t)((gk * 32 + ((lane >> 4) & 1) * 8 + (lane & 7)) * PITCH +
                   ((lane >> 3) & 1) * 16);
    const uint32_t bV = gbase + 2 * KBUF +
        (uint32_t)((gk * 32 + ((lane >> 3) & 1) * 8 + (lane & 7)) * PITCH +
                   (((lane >> 4) & 1) * 8) * 2);

    float acc2[8][4];
    #pragma unroll
    for (int ni = 0; ni < 8; ++ni)
        #pragma unroll
        for (int e = 0; e < 4; ++e) acc2[ni][e] = 0.0f;

    for (int t = 0; t < NTILES; ++t) {
        const int tn = (t + 1 < NTILES) ? t + 1 : 0;
        const uint32_t cur = (uint32_t)((t & 1) * STAGE);
        const uint32_t nxt = (uint32_t)(((t + 1) & 1) * STAGE);

        // ---- cp.async stage t+1 (nxt readers done before last tile's bar) ----
        {
            size_t off = (rowbase + (size_t)tn * TK + crow) * 128 + cj;
            CP16(stBase + nxt,               (const char*)g_khi + off);
            CP16(stBase + nxt + 16,          (const char*)g_khi + off + 16);
            CP16(stBase + nxt + KBUF,        (const char*)g_klo + off);
            CP16(stBase + nxt + KBUF + 16,   (const char*)g_klo + off + 16);
            CP16(stBase + nxt + 2*KBUF,      (const char*)g_vhi + off);
            CP16(stBase + nxt + 2*KBUF + 16, (const char*)g_vhi + off + 16);
            CP16(stBase + nxt + 3*KBUF,      (const char*)g_vlo + off);
            CP16(stBase + nxt + 3*KBUF + 16, (const char*)g_vlo + off + 16);
            CP_COMMIT();
        }

        // ---- GEMM1(t) on K[cur] ----
        float acc1[4][4];
        #pragma unroll
        for (int n = 0; n < 4; ++n)
            #pragma unroll
            for (int e = 0; e < 4; ++e) acc1[n][e] = 0.0f;

        {
            uint32_t Bh[2][4], Bl[2][4];
            LDMX4(Bh[0], bK + cur);
            LDMX4(Bl[0], bK + cur + KBUF);
            #pragma unroll
            for (int s = 0; s < 8; ++s) {
                const int ks = s >> 1, p = s & 1;
                const int cb = s & 1, nb = cb ^ 1;
                if (s < 7) {
                    const int s2 = s + 1;
                    uint32_t bb = bK + cur +
                        (uint32_t)((s2 & 1) * 16 * PITCH + (s2 >> 1) * 32);
                    LDMX4(Bh[nb], bb);
                    LDMX4(Bl[nb], bb + KBUF);
                }
                MMA(acc1[2*p],   qhi[ks], Bh[cb]);
                MMA(acc1[2*p],   qhi[ks], Bl[cb]);
                MMA(acc1[2*p],   qlo[ks], Bh[cb]);
                MMA(acc1[2*p+1], qhi[ks], Bh[cb] + 2);
                MMA(acc1[2*p+1], qhi[ks], Bl[cb] + 2);
                MMA(acc1[2*p+1], qlo[ks], Bh[cb] + 2);
            }
        }

        // ---- GEMM2(t) on V[cur]: exp fused, V frags double-buffered ----
        {
            uint32_t Vh[2][4], Vl[2][4];
            LDMX4T(Vh[0], bV + cur);
            LDMX4T(Vl[0], bV + cur + KBUF);
            uint32_t phi[4], plo[4];
            #pragma unroll
            for (int s = 0; s < 8; ++s) {
                const int k2 = s >> 2, p = s & 3;
                const int cb = s & 1, nb = cb ^ 1;
                if (p == 0) {
                    float e0 = ex2f(acc1[2*k2][0]);
                    float e1 = ex2f(acc1[2*k2][1]);
                    float e2 = ex2f(acc1[2*k2][2]);
                    float e3 = ex2f(acc1[2*k2][3]);
                    split_pack(e0, e1, phi[0], plo[0]);
                    split_pack(e2, e3, phi[1], plo[1]);
                    float f0 = ex2f(acc1[2*k2+1][0]);
                    float f1 = ex2f(acc1[2*k2+1][1]);
                    float f2 = ex2f(acc1[2*k2+1][2]);
                    float f3 = ex2f(acc1[2*k2+1][3]);
                    split_pack(f0, f1, phi[2], plo[2]);
                    split_pack(f2, f3, phi[3], plo[3]);
                }
                if (s < 7) {
                    const int s2 = s + 1;
                    uint32_t bb = bV + cur +
                        (uint32_t)((s2 >> 2) * 16 * PITCH + (s2 & 3) * 32);
                    LDMX4T(Vh[nb], bb);
                    LDMX4T(Vl[nb], bb + KBUF);
                }
                MMA(acc2[2*p],   phi, Vh[cb]);
                MMA(acc2[2*p],   phi, Vl[cb]);
                MMA(acc2[2*p],   plo, Vh[cb]);
                MMA(acc2[2*p+1], phi, Vh[cb] + 2);
                MMA(acc2[2*p+1], phi, Vl[cb] + 2);
                MMA(acc2[2*p+1], plo, Vh[cb] + 2);
            }
        }

        CP_WAIT0();     // nxt landed (this thread)
        GBAR(bar);      // group-local: cur reads done, nxt visible group-wide
    }

    // ---- split-K reduction (group-local, in group's stage region) ----
    float* red = (float*)gmem_sm;
    if (gk == 1) {
        #pragma unroll
        for (int ni = 0; ni < 8; ++ni) {
            int r = m * 16 + (lane >> 2);
            int c = ni * 8 + (lane & 3) * 2;
            *(float2*)&red[r * RED_PITCH + c] =
                make_float2(acc2[ni][0], acc2[ni][1]);
            *(float2*)&red[(r + 8) * RED_PITCH + c] =
                make_float2(acc2[ni][2], acc2[ni][3]);
        }
    }
    GBAR(bar);
    if (gk == 0) {
        #pragma unroll
        for (int ni = 0; ni < 8; ++ni) {
            int r = m * 16 + (lane >> 2);
            int c = ni * 8 + (lane & 3) * 2;
            float2 p0 = *(const float2*)&red[r * RED_PITCH + c];
            float2 p1 = *(const float2*)&red[(r + 8) * RED_PITCH + c];
            int gr = gid * 64 + r;
            *(float2*)&Og[(size_t)gr * DD + c] =
                make_float2(acc2[ni][0] + p0.x, acc2[ni][1] + p0.y);
            *(float2*)&Og[(size_t)(gr + 8) * DD + c] =
                make_float2(acc2[ni][2] + p1.x, acc2[ni][3] + p1.y);
        }
    }
}

extern "C" void kernel_launch(void* const* d_in, const int* in_sizes, int n_in,
                              void* d_out, int out_size)
{
    const float* q = (const float*)d_in[0];
    const float* k = (const float*)d_in[1];
    const float* v = (const float*)d_in[2];
    float* out = (float*)d_out;
    (void)in_sizes; (void)n_in; (void)out_size;

    split_kv_kernel<<<512, 256>>>(k, v);

    cudaFuncSetAttribute(fa_fa14_kernel,
                         cudaFuncAttributeMaxDynamicSharedMemorySize, SM_TOTAL);
    dim3 grid(S_LEN / TQ, B_SZ);   // 32 x 4 = 128 CTAs, one wave
    fa_fa14_kernel<<<grid, NTH, SM_TOTAL>>>(q, out);
}

// round 15
// speedup vs baseline: 1.1451x; 1.1451x over previous
#include <cuda_runtime.h>
#include <cuda_bf16.h>
#include <cstdint>

// out[b,i,:] = sum_j exp(q_i . k_j) * v_j   (B=4, S=4096, D=64, fp32)
// R15: cross-tile pipelining — iteration i runs GEMM1(tile i) and
//      GEMM2(tile i-1) interleaved (two independent MMA streams/warp),
//      hiding the exp/split chain. cp.async from pre-split bf16 globals.

#define S_LEN 4096
#define B_SZ  4
#define DD    64
#define TQ    128
#define TK    64
#define NTH   512
#define NTILES (S_LEN / TK)

#define PITCH 144               // 64 bf16 + 8B pad
#define KBUF  (TK * PITCH)      // 9216 per hi/lo buffer

// K stages: s*2*KBUF (hi), +KBUF (lo).  V stages at SM_V likewise.
#define SM_K  0
#define SM_V  (4 * KBUF)        // 36864
#define QOFF  (8 * KBUF)        // 73728: Q hi; Q lo at QOFF+KBUF2
#define KBUF2 (TQ * PITCH)      // 18432
#define SM_TOTAL (QOFF + 2 * KBUF2)   // 110592
#define RED_PITCH 72

#define LOG2E 1.4426950408889634f

#define NROWS (B_SZ * S_LEN)
__device__ __align__(16) unsigned char g_khi[NROWS * 128];
__device__ __align__(16) unsigned char g_klo[NROWS * 128];
__device__ __align__(16) unsigned char g_vhi[NROWS * 128];
__device__ __align__(16) unsigned char g_vlo[NROWS * 128];

__device__ __forceinline__ uint32_t smem_u32(const void* p) {
    uint32_t a;
    asm("{ .reg .u64 t; cvta.to.shared.u64 t, %1; cvt.u32.u64 %0, t; }" : "=r"(a) : "l"(p));
    return a;
}
#define LDMX4(r, a) \
    asm volatile("ldmatrix.sync.aligned.m8n8.x4.shared.b16 {%0,%1,%2,%3}, [%4];" \
        : "=r"((r)[0]), "=r"((r)[1]), "=r"((r)[2]), "=r"((r)[3]) : "r"(a))
#define LDMX4T(r, a) \
    asm volatile("ldmatrix.sync.aligned.m8n8.x4.trans.shared.b16 {%0,%1,%2,%3}, [%4];" \
        : "=r"((r)[0]), "=r"((r)[1]), "=r"((r)[2]), "=r"((r)[3]) : "r"(a))
#define MMA(c, av, bv) \
    asm volatile("mma.sync.aligned.m16n8k16.row.col.f32.bf16.bf16.f32 " \
        "{%0,%1,%2,%3}, {%4,%5,%6,%7}, {%8,%9}, {%0,%1,%2,%3};" \
        : "+f"((c)[0]), "+f"((c)[1]), "+f"((c)[2]), "+f"((c)[3]) \
        : "r"((av)[0]), "r"((av)[1]), "r"((av)[2]), "r"((av)[3]), \
          "r"((bv)[0]), "r"((bv)[1]))
#define CP16(dst, src) \
    asm volatile("cp.async.cg.shared.global [%0], [%1], 16;" \
        :: "r"(dst), "l"(src) : "memory")
#define CP_COMMIT() asm volatile("cp.async.commit_group;" ::: "memory")
#define CP_WAIT0()  asm volatile("cp.async.wait_group 0;" ::: "memory")

__device__ __forceinline__ float ex2f(float x) {
    float r;
    asm("ex2.approx.ftz.f32 %0, %1;" : "=f"(r) : "f"(x));
    return r;
}
__device__ __forceinline__ void split_pack(float x, float y, uint32_t& hi, uint32_t& lo) {
    asm("cvt.rn.bf16x2.f32 %0, %1, %2;" : "=r"(hi) : "f"(y), "f"(x));
    float xh = __uint_as_float(hi << 16);
    float yh = __uint_as_float(hi & 0xffff0000u);
    asm("cvt.rn.bf16x2.f32 %0, %1, %2;" : "=r"(lo) : "f"(y - yh), "f"(x - xh));
}

// ---------------- pre-pass: split K,V into bf16 hi/lo ----------------
__global__ void __launch_bounds__(256)
split_kv_kernel(const float* __restrict__ k, const float* __restrict__ v)
{
    const int total = NROWS * DD / 4;
    uint2* khi = (uint2*)g_khi;
    uint2* klo = (uint2*)g_klo;
    uint2* vhi = (uint2*)g_vhi;
    uint2* vlo = (uint2*)g_vlo;
    for (int i = blockIdx.x * blockDim.x + threadIdx.x; i < total;
         i += gridDim.x * blockDim.x) {
        float4 a = ((const float4*)k)[i];
        uint32_t h0, l0, h1, l1;
        split_pack(a.x, a.y, h0, l0);
        split_pack(a.z, a.w, h1, l1);
        khi[i] = make_uint2(h0, h1);
        klo[i] = make_uint2(l0, l1);
        float4 c = ((const float4*)v)[i];
        split_pack(c.x, c.y, h0, l0);
        split_pack(c.z, c.w, h1, l1);
        vhi[i] = make_uint2(h0, h1);
        vlo[i] = make_uint2(l0, l1);
    }
}

// ---------------- main kernel ----------------
__global__ void __launch_bounds__(NTH, 1)
fa_fa15_kernel(const float* __restrict__ q, float* __restrict__ out)
{
    extern __shared__ char smem[];
    const uint32_t sb = smem_u32(smem);
    const int tid  = threadIdx.x;
    const int wid  = tid >> 5;
    const int lane = tid & 31;
    const int m    = wid & 7;    // M-group: rows m*16 .. +15
    const int g    = wid >> 3;   // key-group: keys g*32 .. +31 of each tile
    const int b  = blockIdx.y;
    const int q0 = blockIdx.x * TQ;

    const float* Qg = q + ((size_t)b * S_LEN + q0) * DD;
    float*       Og = out + ((size_t)b * S_LEN + q0) * DD;
    const size_t rowbase = (size_t)b * S_LEN;

    // cp.async per-thread: one 16B chunk per hi/lo buffer
    const int crow = tid >> 3;          // 0..63
    const int cj   = (tid & 7) * 16;
    const uint32_t stK = sb + SM_K + (uint32_t)(crow * PITCH + cj);
    const uint32_t stV = sb + SM_V + (uint32_t)(crow * PITCH + cj);

    // ---- prologue: stage Q (x log2e) into dedicated region ----
    {
        #pragma unroll
        for (int i = 0; i < 4; ++i) {
            int f = tid + i * NTH;
            int row = f >> 4, d0 = (f & 15) << 2;
            float4 t = *(const float4*)&Qg[(size_t)row * DD + d0];
            uint32_t h0, l0, h1, l1;
            split_pack(t.x * LOG2E, t.y * LOG2E, h0, l0);
            split_pack(t.z * LOG2E, t.w * LOG2E, h1, l1);
            int off = row * PITCH + d0 * 2;
            *(uint2*)(smem + QOFF + off)         = make_uint2(h0, h1);
            *(uint2*)(smem + QOFF + KBUF2 + off) = make_uint2(l0, l1);
        }
    }
    __syncthreads();

    // persistent Q-hi A-frags; Q-lo stays in smem (reloaded per step)
    uint32_t qhi[4][4];
    const uint32_t aQhi = sb + QOFF +
        (uint32_t)((m * 16 + (lane & 15)) * PITCH + (lane >> 4) * 16);
    const uint32_t aQlo = aQhi + KBUF2;
    #pragma unroll
    for (int ks = 0; ks < 4; ++ks) LDMX4(qhi[ks], aQhi + ks * 32);

    // stage K0,V0 -> stage 0; K1 -> stage 1
    {
        size_t off0 = (rowbase + crow) * 128 + cj;
        size_t off1 = (rowbase + (size_t)TK + crow) * 128 + cj;
        CP16(stK,                 (const char*)g_khi + off0);
        CP16(stK + KBUF,          (const char*)g_klo + off0);
        CP16(stV,                 (const char*)g_vhi + off0);
        CP16(stV + KBUF,          (const char*)g_vlo + off0);
        CP16(stK + 2 * KBUF,        (const char*)g_khi + off1);
        CP16(stK + 2 * KBUF + KBUF, (const char*)g_klo + off1);
        CP_COMMIT();
        CP_WAIT0();
    }
    __syncthreads();

    // per-lane B-operand bases (stage offset added at use)
    const uint32_t bK = sb + SM_K +
        (uint32_t)((g * 32 + ((lane >> 4) & 1) * 8 + (lane & 7)) * PITCH +
                   ((lane >> 3) & 1) * 16);
    const uint32_t bV = sb + SM_V +
        (uint32_t)((g * 32 + ((lane >> 3) & 1) * 8 + (lane & 7)) * PITCH +
                   (((lane >> 4) & 1) * 8) * 2);

    float acc2[8][4];
    #pragma unroll
    for (int ni = 0; ni < 8; ++ni)
        #pragma unroll
        for (int e = 0; e < 4; ++e) acc2[ni][e] = 0.0f;

    float accP[4][4];   // S of tile i-1 (pre-exp)

    // ---- prologue GEMM1(tile 0) -> accP ----
    #pragma unroll
    for (int n = 0; n < 4; ++n)
        #pragma unroll
        for (int e = 0; e < 4; ++e) accP[n][e] = 0.0f;
    #pragma unroll
    for (int s = 0; s < 8; ++s) {
        const int ks = s >> 1, pk = s & 1;
        uint32_t Bh[4], Bl[4], ql[4];
        uint32_t bb = bK + (uint32_t)(pk * 16 * PITCH + ks * 32);
        LDMX4(Bh, bb);
        LDMX4(Bl, bb + KBUF);
        LDMX4(ql, aQlo + ks * 32);
        MMA(accP[2*pk],   qhi[ks], Bh);
        MMA(accP[2*pk+1], qhi[ks], Bh + 2);
        MMA(accP[2*pk],   qhi[ks], Bl);
        MMA(accP[2*pk+1], qhi[ks], Bl + 2);
        MMA(accP[2*pk],   ql, Bh);
        MMA(accP[2*pk+1], ql, Bh + 2);
    }
    __syncthreads();   // all warps done with K-stage 0 before iter 1 overwrites it

    // ---- main pipelined loop: iteration i = GEMM1(i) + GEMM2(i-1) ----
    for (int i = 1; i < NTILES; ++i) {
        const int ip1 = (i + 1 < NTILES) ? i + 1 : 0;
        const uint32_t curK  = (uint32_t)((i & 1) * 2 * KBUF);
        const uint32_t nxtK  = (uint32_t)(((i + 1) & 1) * 2 * KBUF);
        const uint32_t prevV = (uint32_t)(((i - 1) & 1) * 2 * KBUF);
        const uint32_t curV  = (uint32_t)((i & 1) * 2 * KBUF);

        // prefetch K(i+1), V(i)
        {
            size_t offK = (rowbase + (size_t)ip1 * TK + crow) * 128 + cj;
            size_t offV = (rowbase + (size_t)i   * TK + crow) * 128 + cj;
            CP16(stK + nxtK,        (const char*)g_khi + offK);
            CP16(stK + nxtK + KBUF, (const char*)g_klo + offK);
            CP16(stV + curV,        (const char*)g_vhi + offV);
            CP16(stV + curV + KBUF, (const char*)g_vlo + offV);
            CP_COMMIT();
        }

        float accN[4][4];
        #pragma unroll
        for (int n = 0; n < 4; ++n)
            #pragma unroll
            for (int e = 0; e < 4; ++e) accN[n][e] = 0.0f;

        uint32_t phi[4], plo[4];
        #pragma unroll
        for (int s = 0; s < 8; ++s) {
            const int ks = s >> 1, pk = s & 1;   // GEMM1 indices
            const int k2 = s >> 2, pv = s & 3;   // GEMM2 indices
            uint32_t Bh[4], Bl[4], Vh[4], Vl[4], ql[4];
            uint32_t bbk = bK + curK + (uint32_t)(pk * 16 * PITCH + ks * 32);
            uint32_t bbv = bV + prevV + (uint32_t)(k2 * 16 * PITCH + pv * 32);
            LDMX4(Bh, bbk);
            LDMX4(Bl, bbk + KBUF);
            LDMX4T(Vh, bbv);
            LDMX4T(Vl, bbv + KBUF);
            LDMX4(ql, aQlo + ks * 32);
            if (pv == 0) {   // exp/split of tile i-1's 16-key group k2
                float e0 = ex2f(accP[2*k2][0]);
                float e1 = ex2f(accP[2*k2][1]);
                float e2 = ex2f(accP[2*k2][2]);
                float e3 = ex2f(accP[2*k2][3]);
                split_pack(e0, e1, phi[0], plo[0]);
                split_pack(e2, e3, phi[1], plo[1]);
                float f0 = ex2f(accP[2*k2+1][0]);
                float f1 = ex2f(accP[2*k2+1][1]);
                float f2 = ex2f(accP[2*k2+1][2]);
                float f3 = ex2f(accP[2*k2+1][3]);
                split_pack(f0, f1, phi[2], plo[2]);
                split_pack(f2, f3, phi[3], plo[3]);
            }
            // two independent MMA streams, interleaved
            MMA(accN[2*pk],   qhi[ks], Bh);      MMA(acc2[2*pv],   phi, Vh);
            MMA(accN[2*pk+1], qhi[ks], Bh + 2);  MMA(acc2[2*pv+1], phi, Vh + 2);
            MMA(accN[2*pk],   qhi[ks], Bl);      MMA(acc2[2*pv],   phi, Vl);
            MMA(accN[2*pk+1], qhi[ks], Bl + 2);  MMA(acc2[2*pv+1], phi, Vl + 2);
            MMA(accN[2*pk],   ql, Bh);           MMA(acc2[2*pv],   plo, Vh);
            MMA(accN[2*pk+1], ql, Bh + 2);       MMA(acc2[2*pv+1], plo, Vh + 2);
        }

        CP_WAIT0();
        __syncthreads();
        #pragma unroll
        for (int n = 0; n < 4; ++n)
            #pragma unroll
            for (int e = 0; e < 4; ++e) accP[n][e] = accN[n][e];
    }

    // ---- epilogue: GEMM2(tile NTILES-1) ----
    {
        const uint32_t prevV = (uint32_t)(((NTILES - 1) & 1) * 2 * KBUF);
        uint32_t phi[4], plo[4];
        #pragma unroll
        for (int s = 0; s < 8; ++s) {
            const int k2 = s >> 2, pv = s & 3;
            uint32_t Vh[4], Vl[4];
            uint32_t bbv = bV + prevV + (uint32_t)(k2 * 16 * PITCH + pv * 32);
            LDMX4T(Vh, bbv);
            LDMX4T(Vl, bbv + KBUF);
            if (pv == 0) {
                float e0 = ex2f(accP[2*k2][0]);
                float e1 = ex2f(accP[2*k2][1]);
                float e2 = ex2f(accP[2*k2][2]);
                float e3 = ex2f(accP[2*k2][3]);
                split_pack(e0, e1, phi[0], plo[0]);
                split_pack(e2, e3, phi[1], plo[1]);
                float f0 = ex2f(accP[2*k2+1][0]);
                float f1 = ex2f(accP[2*k2+1][1]);
                float f2 = ex2f(accP[2*k2+1][2]);
                float f3 = ex2f(accP[2*k2+1][3]);
                split_pack(f0, f1, phi[2], plo[2]);
                split_pack(f2, f3, phi[3], plo[3]);
            }
            MMA(acc2[2*pv],   phi, Vh);
            MMA(acc2[2*pv+1], phi, Vh + 2);
            MMA(acc2[2*pv],   phi, Vl);
            MMA(acc2[2*pv+1], phi, Vl + 2);
            MMA(acc2[2*pv],   plo, Vh);
            MMA(acc2[2*pv+1], plo, Vh + 2);
        }
    }
    __syncthreads();   // stages dead; reduction region reuse

    // ---- split-K reduction: g==1 -> smem, g==0 adds and stores ----
    float* red = (float*)smem;
    if (g == 1) {
        #pragma unroll
        for (int ni = 0; ni < 8; ++ni) {
            int r = m * 16 + (lane >> 2);
            int c = ni * 8 + (lane & 3) * 2;
            *(float2*)&red[r * RED_PITCH + c] =
                make_float2(acc2[ni][0], acc2[ni][1]);
            *(float2*)&red[(r + 8) * RED_PITCH + c] =
                make_float2(acc2[ni][2], acc2[ni][3]);
        }
    }
    __syncthreads();
    if (g == 0) {
        #pragma unroll
        for (int ni = 0; ni < 8; ++ni) {
            int r = m * 16 + (lane >> 2);
            int c = ni * 8 + (lane & 3) * 2;
            float2 p0 = *(const float2*)&red[r * RED_PITCH + c];
            float2 p1 = *(const float2*)&red[(r + 8) * RED_PITCH + c];
            *(float2*)&Og[(size_t)r * DD + c] =
                make_float2(acc2[ni][0] + p0.x, acc2[ni][1] + p0.y);
            *(float2*)&Og[(size_t)(r + 8) * DD + c] =
                make_float2(acc2[ni][2] + p1.x, acc2[ni][3] + p1.y);
        }
    }
}

extern "C" void kernel_launch(void* const* d_in, const int* in_sizes, int n_in,
                              void* d_out, int out_size)
{
    const float* q = (const float*)d_in[0];
    const float* k = (const float*)d_in[1];
    const float* v = (const float*)d_in[2];
    float* out = (float*)d_out;
    (void)in_sizes; (void)n_in; (void)out_size;

    split_kv_kernel<<<512, 256>>>(k, v);

    cudaFuncSetAttribute(fa_fa15_kernel,
                         cudaFuncAttributeMaxDynamicSharedMemorySize, SM_TOTAL);
    dim3 grid(S_LEN / TQ, B_SZ);   // 32 x 4 = 128 CTAs, one wave
    fa_fa15_kernel<<<grid, NTH, SM_TOTAL>>>(q, out);
}

// round 16
// speedup vs baseline: 1.2378x; 1.0810x over previous
#include <cuda_runtime.h>
#include <cuda_bf16.h>
#include <cstdint>

// out[b,i,:] = sum_j exp(q_i . k_j) * v_j   (B=4, S=4096, D=64, fp32)
// R16: R13 skeleton (pre-split bf16 K/V globals + cp.async staging) with a
//      4-stage pipeline, prefetch distance 2, wait+barrier every 2 tiles.

#define S_LEN 4096
#define B_SZ  4
#define DD    64
#define TQ    128
#define TK    64
#define NTH   512
#define NTILES (S_LEN / TK)

#define PITCH 144               // 64 bf16 + 8B pad
#define KBUF  (TK * PITCH)      // 9216 per hi/lo buffer
#define SSTR  (2 * KBUF)        // stage stride (hi+lo)

#define SM_K  0                 // 4 K stages: 73728
#define SM_V  (4 * SSTR)        // 4 V stages: 73728
#define SM_TOTAL (8 * SSTR)     // 147456 B
#define RED_PITCH 72            // reduction aliases base region

#define LOG2E 1.4426950408889634f

#define NROWS (B_SZ * S_LEN)
__device__ __align__(16) unsigned char g_khi[NROWS * 128];
__device__ __align__(16) unsigned char g_klo[NROWS * 128];
__device__ __align__(16) unsigned char g_vhi[NROWS * 128];
__device__ __align__(16) unsigned char g_vlo[NROWS * 128];

__device__ __forceinline__ uint32_t smem_u32(const void* p) {
    uint32_t a;
    asm("{ .reg .u64 t; cvta.to.shared.u64 t, %1; cvt.u32.u64 %0, t; }" : "=r"(a) : "l"(p));
    return a;
}
#define LDMX4(r, a) \
    asm volatile("ldmatrix.sync.aligned.m8n8.x4.shared.b16 {%0,%1,%2,%3}, [%4];" \
        : "=r"((r)[0]), "=r"((r)[1]), "=r"((r)[2]), "=r"((r)[3]) : "r"(a))
#define LDMX4T(r, a) \
    asm volatile("ldmatrix.sync.aligned.m8n8.x4.trans.shared.b16 {%0,%1,%2,%3}, [%4];" \
        : "=r"((r)[0]), "=r"((r)[1]), "=r"((r)[2]), "=r"((r)[3]) : "r"(a))
#define MMA(c, av, bv) \
    asm volatile("mma.sync.aligned.m16n8k16.row.col.f32.bf16.bf16.f32 " \
        "{%0,%1,%2,%3}, {%4,%5,%6,%7}, {%8,%9}, {%0,%1,%2,%3};" \
        : "+f"((c)[0]), "+f"((c)[1]), "+f"((c)[2]), "+f"((c)[3]) \
        : "r"((av)[0]), "r"((av)[1]), "r"((av)[2]), "r"((av)[3]), \
          "r"((bv)[0]), "r"((bv)[1]))
#define CP16(dst, src) \
    asm volatile("cp.async.cg.shared.global [%0], [%1], 16;" \
        :: "r"(dst), "l"(src) : "memory")
#define CP_COMMIT() asm volatile("cp.async.commit_group;" ::: "memory")
#define CP_WAIT0()  asm volatile("cp.async.wait_group 0;" ::: "memory")

__device__ __forceinline__ float ex2f(float x) {
    float r;
    asm("ex2.approx.ftz.f32 %0, %1;" : "=f"(r) : "f"(x));
    return r;
}
__device__ __forceinline__ void split_pack(float x, float y, uint32_t& hi, uint32_t& lo) {
    asm("cvt.rn.bf16x2.f32 %0, %1, %2;" : "=r"(hi) : "f"(y), "f"(x));
    float xh = __uint_as_float(hi << 16);
    float yh = __uint_as_float(hi & 0xffff0000u);
    asm("cvt.rn.bf16x2.f32 %0, %1, %2;" : "=r"(lo) : "f"(y - yh), "f"(x - xh));
}

// ---------------- pre-pass: split K,V into bf16 hi/lo ----------------
__global__ void __launch_bounds__(256)
split_kv_kernel(const float* __restrict__ k, const float* __restrict__ v)
{
    const int total = NROWS * DD / 4;
    uint2* khi = (uint2*)g_khi;
    uint2* klo = (uint2*)g_klo;
    uint2* vhi = (uint2*)g_vhi;
    uint2* vlo = (uint2*)g_vlo;
    for (int i = blockIdx.x * blockDim.x + threadIdx.x; i < total;
         i += gridDim.x * blockDim.x) {
        float4 a = ((const float4*)k)[i];
        uint32_t h0, l0, h1, l1;
        split_pack(a.x, a.y, h0, l0);
        split_pack(a.z, a.w, h1, l1);
        khi[i] = make_uint2(h0, h1);
        klo[i] = make_uint2(l0, l1);
        float4 c = ((const float4*)v)[i];
        split_pack(c.x, c.y, h0, l0);
        split_pack(c.z, c.w, h1, l1);
        vhi[i] = make_uint2(h0, h1);
        vlo[i] = make_uint2(l0, l1);
    }
}

// ---------------- main kernel ----------------
__global__ void __launch_bounds__(NTH, 1)
fa_fa16_kernel(const float* __restrict__ q, float* __restrict__ out)
{
    extern __shared__ char smem[];
    const uint32_t sb = smem_u32(smem);
    const int tid  = threadIdx.x;
    const int wid  = tid >> 5;
    const int lane = tid & 31;
    const int m    = wid & 7;    // M-group: rows m*16 .. +15
    const int g    = wid >> 3;   // key-group: keys g*32 .. +31
    const int b  = blockIdx.y;
    const int q0 = blockIdx.x * TQ;

    const float* Qg = q + ((size_t)b * S_LEN + q0) * DD;
    float*       Og = out + ((size_t)b * S_LEN + q0) * DD;
    const size_t rowbase = (size_t)b * S_LEN;

    // cp.async per-thread: one 16B chunk per hi/lo buffer
    const int crow = tid >> 3;          // 0..63
    const int cj   = (tid & 7) * 16;
    const uint32_t stK = sb + SM_K + (uint32_t)(crow * PITCH + cj);
    const uint32_t stV = sb + SM_V + (uint32_t)(crow * PITCH + cj);

    // ---- prologue: stage Q (x log2e), grab persistent A-frags ----
    {
        #pragma unroll
        for (int i = 0; i < 4; ++i) {
            int f = tid + i * NTH;
            int row = f >> 4, d0 = (f & 15) << 2;
            float4 t = *(const float4*)&Qg[(size_t)row * DD + d0];
            uint32_t h0, l0, h1, l1;
            split_pack(t.x * LOG2E, t.y * LOG2E, h0, l0);
            split_pack(t.z * LOG2E, t.w * LOG2E, h1, l1);
            int off = row * PITCH + d0 * 2;
            *(uint2*)(smem + off)              = make_uint2(h0, h1);
            *(uint2*)(smem + TQ * PITCH + off) = make_uint2(l0, l1);
        }
    }
    __syncthreads();

    uint32_t qhi[4][4], qlo[4][4];
    {
        const uint32_t aQ = sb +
            (uint32_t)((m * 16 + (lane & 15)) * PITCH + (lane >> 4) * 16);
        #pragma unroll
        for (int ks = 0; ks < 4; ++ks) {
            LDMX4(qhi[ks], aQ + ks * 32);
            LDMX4(qlo[ks], aQ + TQ * PITCH + ks * 32);
        }
    }
    __syncthreads();    // Q region free (aliased by K stages 0-1)

    // stage tiles 0 and 1 into stages 0 and 1
    {
        #pragma unroll
        for (int s0 = 0; s0 < 2; ++s0) {
            size_t off = (rowbase + (size_t)s0 * TK + crow) * 128 + cj;
            uint32_t st = (uint32_t)(s0 * SSTR);
            CP16(stK + st,        (const char*)g_khi + off);
            CP16(stK + st + KBUF, (const char*)g_klo + off);
            CP16(stV + st,        (const char*)g_vhi + off);
            CP16(stV + st + KBUF, (const char*)g_vlo + off);
        }
        CP_COMMIT();
        CP_WAIT0();
    }
    __syncthreads();

    // per-lane B-operand bases within a stage
    const uint32_t bK = sb + SM_K +
        (uint32_t)((g * 32 + ((lane >> 4) & 1) * 8 + (lane & 7)) * PITCH +
                   ((lane >> 3) & 1) * 16);
    const uint32_t bV = sb + SM_V +
        (uint32_t)((g * 32 + ((lane >> 3) & 1) * 8 + (lane & 7)) * PITCH +
                   (((lane >> 4) & 1) * 8) * 2);

    float acc2[8][4];
    #pragma unroll
    for (int ni = 0; ni < 8; ++ni)
        #pragma unroll
        for (int e = 0; e < 4; ++e) acc2[ni][e] = 0.0f;

    for (int t = 0; t < NTILES; ++t) {
        const uint32_t cur = (uint32_t)((t & 3) * SSTR);

        // ---- prefetch tile t+2 into stage (t+2)&3 ----
        if (t + 2 < NTILES) {
            const uint32_t nst = (uint32_t)(((t + 2) & 3) * SSTR);
            size_t off = (rowbase + (size_t)(t + 2) * TK + crow) * 128 + cj;
            CP16(stK + nst,        (const char*)g_khi + off);
            CP16(stK + nst + KBUF, (const char*)g_klo + off);
            CP16(stV + nst,        (const char*)g_vhi + off);
            CP16(stV + nst + KBUF, (const char*)g_vlo + off);
            CP_COMMIT();
        }

        // ---- GEMM1(t) on K[cur] ----
        float acc1[4][4];
        #pragma unroll
        for (int n = 0; n < 4; ++n)
            #pragma unroll
            for (int e = 0; e < 4; ++e) acc1[n][e] = 0.0f;

        {
            uint32_t Bh[2][4], Bl[2][4];
            LDMX4(Bh[0], bK + cur);
            LDMX4(Bl[0], bK + cur + KBUF);
            #pragma unroll
            for (int s = 0; s < 8; ++s) {
                const int ks = s >> 1, p = s & 1;
                const int cb = s & 1, nb = cb ^ 1;
                if (s < 7) {
                    const int s2 = s + 1;
                    uint32_t bb = bK + cur +
                        (uint32_t)((s2 & 1) * 16 * PITCH + (s2 >> 1) * 32);
                    LDMX4(Bh[nb], bb);
                    LDMX4(Bl[nb], bb + KBUF);
                }
                MMA(acc1[2*p],   qhi[ks], Bh[cb]);
                MMA(acc1[2*p],   qhi[ks], Bl[cb]);
                MMA(acc1[2*p],   qlo[ks], Bh[cb]);
                MMA(acc1[2*p+1], qhi[ks], Bh[cb] + 2);
                MMA(acc1[2*p+1], qhi[ks], Bl[cb] + 2);
                MMA(acc1[2*p+1], qlo[ks], Bh[cb] + 2);
            }
        }

        // ---- GEMM2(t) on V[cur]: exp fused, V frags double-buffered ----
        {
            uint32_t Vh[2][4], Vl[2][4];
            LDMX4T(Vh[0], bV + cur);
            LDMX4T(Vl[0], bV + cur + KBUF);
            uint32_t phi[4], plo[4];
            #pragma unroll
            for (int s = 0; s < 8; ++s) {
                const int k2 = s >> 2, p = s & 3;
                const int cb = s & 1, nb = cb ^ 1;
                if (p == 0) {
                    float e0 = ex2f(acc1[2*k2][0]);
                    float e1 = ex2f(acc1[2*k2][1]);
                    float e2 = ex2f(acc1[2*k2][2]);
                    float e3 = ex2f(acc1[2*k2][3]);
                    split_pack(e0, e1, phi[0], plo[0]);
                    split_pack(e2, e3, phi[1], plo[1]);
                    float f0 = ex2f(acc1[2*k2+1][0]);
                    float f1 = ex2f(acc1[2*k2+1][1]);
                    float f2 = ex2f(acc1[2*k2+1][2]);
                    float f3 = ex2f(acc1[2*k2+1][3]);
                    split_pack(f0, f1, phi[2], plo[2]);
                    split_pack(f2, f3, phi[3], plo[3]);
                }
                if (s < 7) {
                    const int s2 = s + 1;
                    uint32_t bb = bV + cur +
                        (uint32_t)((s2 >> 2) * 16 * PITCH + (s2 & 3) * 32);
                    LDMX4T(Vh[nb], bb);
                    LDMX4T(Vl[nb], bb + KBUF);
                }
                MMA(acc2[2*p],   phi, Vh[cb]);
                MMA(acc2[2*p],   phi, Vl[cb]);
                MMA(acc2[2*p],   plo, Vh[cb]);
                MMA(acc2[2*p+1], phi, Vh[cb] + 2);
                MMA(acc2[2*p+1], phi, Vl[cb] + 2);
                MMA(acc2[2*p+1], plo, Vh[cb] + 2);
            }
        }

        // ---- wait + barrier only every 2 tiles ----
        if (t & 1) {
            CP_WAIT0();
            __syncthreads();
        }
    }

    // ---- split-K reduction: g==1 -> smem, g==0 adds and stores ----
    __syncthreads();
    float* red = (float*)smem;
    if (g == 1) {
        #pragma unroll
        for (int ni = 0; ni < 8; ++ni) {
            int r = m * 16 + (lane >> 2);
            int c = ni * 8 + (lane & 3) * 2;
            *(float2*)&red[r * RED_PITCH + c] =
                make_float2(acc2[ni][0], acc2[ni][1]);
            *(float2*)&red[(r + 8) * RED_PITCH + c] =
                make_float2(acc2[ni][2], acc2[ni][3]);
        }
    }
    __syncthreads();
    if (g == 0) {
        #pragma unroll
        for (int ni = 0; ni < 8; ++ni) {
            int r = m * 16 + (lane >> 2);
            int c = ni * 8 + (lane & 3) * 2;
            float2 p0 = *(const float2*)&red[r * RED_PITCH + c];
            float2 p1 = *(const float2*)&red[(r + 8) * RED_PITCH + c];
            *(float2*)&Og[(size_t)r * DD + c] =
                make_float2(acc2[ni][0] + p0.x, acc2[ni][1] + p0.y);
            *(float2*)&Og[(size_t)(r + 8) * DD + c] =
                make_float2(acc2[ni][2] + p1.x, acc2[ni][3] + p1.y);
        }
    }
}

extern "C" void kernel_launch(void* const* d_in, const int* in_sizes, int n_in,
                              void* d_out, int out_size)
{
    const float* q = (const float*)d_in[0];
    const float* k = (const float*)d_in[1];
    const float* v = (const float*)d_in[2];
    float* out = (float*)d_out;
    (void)in_sizes; (void)n_in; (void)out_size;

    split_kv_kernel<<<512, 256>>>(k, v);

    cudaFuncSetAttribute(fa_fa16_kernel,
                         cudaFuncAttributeMaxDynamicSharedMemorySize, SM_TOTAL);
    dim3 grid(S_LEN / TQ, B_SZ);   // 32 x 4 = 128 CTAs, one wave
    fa_fa16_kernel<<<grid, NTH, SM_TOTAL>>>(q, out);
}

// round 17
// speedup vs baseline: 1.2472x; 1.0076x over previous
#include <cuda_runtime.h>
#include <cuda_bf16.h>
#include <cstdint>

// out[b,i,:] = sum_j exp(q_i . k_j) * v_j   (B=4, S=4096, D=64, fp32)
// R17: 6-stage pipeline, prefetch distance 3, wait+barrier every 3 tiles.
//      GEMM1 reordered p-outer/ks-inner (earlier acc1 finalize for exp).
//      Pre-split bf16 K/V globals + cp.async staging (R13/R16 skeleton).

#define S_LEN 4096
#define B_SZ  4
#define DD    64
#define TQ    128
#define TK    64
#define NTH   512
#define NTILES (S_LEN / TK)

#define PITCH 144               // 64 bf16 + 8B pad
#define KBUF  (TK * PITCH)      // 9216 per hi/lo buffer
#define SSTR  (2 * KBUF)        // stage stride (hi+lo) = 18432
#define NSTG  6

#define SM_K  0                 // 6 K stages: 110592
#define SM_V  (NSTG * SSTR)     // 6 V stages: 110592
#define SM_TOTAL (2 * NSTG * SSTR)   // 221184 B
#define RED_PITCH 72

#define LOG2E 1.4426950408889634f

#define NROWS (B_SZ * S_LEN)
__device__ __align__(16) unsigned char g_khi[NROWS * 128];
__device__ __align__(16) unsigned char g_klo[NROWS * 128];
__device__ __align__(16) unsigned char g_vhi[NROWS * 128];
__device__ __align__(16) unsigned char g_vlo[NROWS * 128];

__device__ __forceinline__ uint32_t smem_u32(const void* p) {
    uint32_t a;
    asm("{ .reg .u64 t; cvta.to.shared.u64 t, %1; cvt.u32.u64 %0, t; }" : "=r"(a) : "l"(p));
    return a;
}
#define LDMX4(r, a) \
    asm volatile("ldmatrix.sync.aligned.m8n8.x4.shared.b16 {%0,%1,%2,%3}, [%4];" \
        : "=r"((r)[0]), "=r"((r)[1]), "=r"((r)[2]), "=r"((r)[3]) : "r"(a))
#define LDMX4T(r, a) \
    asm volatile("ldmatrix.sync.aligned.m8n8.x4.trans.shared.b16 {%0,%1,%2,%3}, [%4];" \
        : "=r"((r)[0]), "=r"((r)[1]), "=r"((r)[2]), "=r"((r)[3]) : "r"(a))
#define MMA(c, av, bv) \
    asm volatile("mma.sync.aligned.m16n8k16.row.col.f32.bf16.bf16.f32 " \
        "{%0,%1,%2,%3}, {%4,%5,%6,%7}, {%8,%9}, {%0,%1,%2,%3};" \
        : "+f"((c)[0]), "+f"((c)[1]), "+f"((c)[2]), "+f"((c)[3]) \
        : "r"((av)[0]), "r"((av)[1]), "r"((av)[2]), "r"((av)[3]), \
          "r"((bv)[0]), "r"((bv)[1]))
#define CP16(dst, src) \
    asm volatile("cp.async.cg.shared.global [%0], [%1], 16;" \
        :: "r"(dst), "l"(src) : "memory")
#define CP_COMMIT() asm volatile("cp.async.commit_group;" ::: "memory")
#define CP_WAIT0()  asm volatile("cp.async.wait_group 0;" ::: "memory")

__device__ __forceinline__ float ex2f(float x) {
    float r;
    asm("ex2.approx.ftz.f32 %0, %1;" : "=f"(r) : "f"(x));
    return r;
}
__device__ __forceinline__ void split_pack(float x, float y, uint32_t& hi, uint32_t& lo) {
    asm("cvt.rn.bf16x2.f32 %0, %1, %2;" : "=r"(hi) : "f"(y), "f"(x));
    float xh = __uint_as_float(hi << 16);
    float yh = __uint_as_float(hi & 0xffff0000u);
    asm("cvt.rn.bf16x2.f32 %0, %1, %2;" : "=r"(lo) : "f"(y - yh), "f"(x - xh));
}

// ---------------- pre-pass: split K,V into bf16 hi/lo ----------------
__global__ void __launch_bounds__(256)
split_kv_kernel(const float* __restrict__ k, const float* __restrict__ v)
{
    const int total = NROWS * DD / 4;
    uint2* khi = (uint2*)g_khi;
    uint2* klo = (uint2*)g_klo;
    uint2* vhi = (uint2*)g_vhi;
    uint2* vlo = (uint2*)g_vlo;
    for (int i = blockIdx.x * blockDim.x + threadIdx.x; i < total;
         i += gridDim.x * blockDim.x) {
        float4 a = ((const float4*)k)[i];
        uint32_t h0, l0, h1, l1;
        split_pack(a.x, a.y, h0, l0);
        split_pack(a.z, a.w, h1, l1);
        khi[i] = make_uint2(h0, h1);
        klo[i] = make_uint2(l0, l1);
        float4 c = ((const float4*)v)[i];
        split_pack(c.x, c.y, h0, l0);
        split_pack(c.z, c.w, h1, l1);
        vhi[i] = make_uint2(h0, h1);
        vlo[i] = make_uint2(l0, l1);
    }
}

// ---------------- main kernel ----------------
__global__ void __launch_bounds__(NTH, 1)
fa_fa17_kernel(const float* __restrict__ q, float* __restrict__ out)
{
    extern __shared__ char smem[];
    const uint32_t sb = smem_u32(smem);
    const int tid  = threadIdx.x;
    const int wid  = tid >> 5;
    const int lane = tid & 31;
    const int m    = wid & 7;    // M-group: rows m*16 .. +15
    const int g    = wid >> 3;   // key-group: keys g*32 .. +31
    const int b  = blockIdx.y;
    const int q0 = blockIdx.x * TQ;

    const float* Qg = q + ((size_t)b * S_LEN + q0) * DD;
    float*       Og = out + ((size_t)b * S_LEN + q0) * DD;
    const size_t rowbase = (size_t)b * S_LEN;

    const int crow = tid >> 3;          // 0..63
    const int cj   = (tid & 7) * 16;
    const uint32_t stK = sb + SM_K + (uint32_t)(crow * PITCH + cj);
    const uint32_t stV = sb + SM_V + (uint32_t)(crow * PITCH + cj);

    // ---- prologue: stage Q (x log2e) into base region, grab A-frags ----
    {
        #pragma unroll
        for (int i = 0; i < 4; ++i) {
            int f = tid + i * NTH;
            int row = f >> 4, d0 = (f & 15) << 2;
            float4 t = *(const float4*)&Qg[(size_t)row * DD + d0];
            uint32_t h0, l0, h1, l1;
            split_pack(t.x * LOG2E, t.y * LOG2E, h0, l0);
            split_pack(t.z * LOG2E, t.w * LOG2E, h1, l1);
            int off = row * PITCH + d0 * 2;
            *(uint2*)(smem + off)              = make_uint2(h0, h1);
            *(uint2*)(smem + TQ * PITCH + off) = make_uint2(l0, l1);
        }
    }
    __syncthreads();

    uint32_t qhi[4][4], qlo[4][4];
    {
        const uint32_t aQ = sb +
            (uint32_t)((m * 16 + (lane & 15)) * PITCH + (lane >> 4) * 16);
        #pragma unroll
        for (int ks = 0; ks < 4; ++ks) {
            LDMX4(qhi[ks], aQ + ks * 32);
            LDMX4(qlo[ks], aQ + TQ * PITCH + ks * 32);
        }
    }
    __syncthreads();    // Q region free (aliased by K stages 0-1)

    // stage tiles 0,1,2 into stages 0,1,2
    {
        #pragma unroll
        for (int s0 = 0; s0 < 3; ++s0) {
            size_t off = (rowbase + (size_t)s0 * TK + crow) * 128 + cj;
            uint32_t st = (uint32_t)(s0 * SSTR);
            CP16(stK + st,        (const char*)g_khi + off);
            CP16(stK + st + KBUF, (const char*)g_klo + off);
            CP16(stV + st,        (const char*)g_vhi + off);
            CP16(stV + st + KBUF, (const char*)g_vlo + off);
        }
        CP_COMMIT();
        CP_WAIT0();
    }
    __syncthreads();

    const uint32_t bK = sb + SM_K +
        (uint32_t)((g * 32 + ((lane >> 4) & 1) * 8 + (lane & 7)) * PITCH +
                   ((lane >> 3) & 1) * 16);
    const uint32_t bV = sb + SM_V +
        (uint32_t)((g * 32 + ((lane >> 3) & 1) * 8 + (lane & 7)) * PITCH +
                   (((lane >> 4) & 1) * 8) * 2);

    float acc2[8][4];
    #pragma unroll
    for (int ni = 0; ni < 8; ++ni)
        #pragma unroll
        for (int e = 0; e < 4; ++e) acc2[ni][e] = 0.0f;

    int stage = 0;   // t % 6
    for (int t = 0; t < NTILES; ++t) {
        const uint32_t cur = (uint32_t)(stage * SSTR);

        // ---- prefetch tile t+3 into stage (t+3)%6 ----
        if (t + 3 < NTILES) {
            int ns = stage + 3; if (ns >= NSTG) ns -= NSTG;
            const uint32_t nst = (uint32_t)(ns * SSTR);
            size_t off = (rowbase + (size_t)(t + 3) * TK + crow) * 128 + cj;
            CP16(stK + nst,        (const char*)g_khi + off);
            CP16(stK + nst + KBUF, (const char*)g_klo + off);
            CP16(stV + nst,        (const char*)g_vhi + off);
            CP16(stV + nst + KBUF, (const char*)g_vlo + off);
            CP_COMMIT();
        }

        // ---- GEMM1(t) on K[cur]: p-outer, ks-inner (early acc1 finalize) ----
        float acc1[4][4];
        #pragma unroll
        for (int n = 0; n < 4; ++n)
            #pragma unroll
            for (int e = 0; e < 4; ++e) acc1[n][e] = 0.0f;

        {
            uint32_t Bh[2][4], Bl[2][4];
            LDMX4(Bh[0], bK + cur);
            LDMX4(Bl[0], bK + cur + KBUF);
            #pragma unroll
            for (int s = 0; s < 8; ++s) {
                const int p = s >> 2, ks = s & 3;   // p-outer
                const int cb = s & 1, nb = cb ^ 1;
                if (s < 7) {
                    const int s2 = s + 1;
                    uint32_t bb = bK + cur +
                        (uint32_t)((s2 >> 2) * 16 * PITCH + (s2 & 3) * 32);
                    LDMX4(Bh[nb], bb);
                    LDMX4(Bl[nb], bb + KBUF);
                }
                MMA(acc1[2*p],   qhi[ks], Bh[cb]);
                MMA(acc1[2*p],   qhi[ks], Bl[cb]);
                MMA(acc1[2*p],   qlo[ks], Bh[cb]);
                MMA(acc1[2*p+1], qhi[ks], Bh[cb] + 2);
                MMA(acc1[2*p+1], qhi[ks], Bl[cb] + 2);
                MMA(acc1[2*p+1], qlo[ks], Bh[cb] + 2);
            }
        }

        // ---- GEMM2(t) on V[cur]: exp fused, V frags double-buffered ----
        {
            uint32_t Vh[2][4], Vl[2][4];
            LDMX4T(Vh[0], bV + cur);
            LDMX4T(Vl[0], bV + cur + KBUF);
            uint32_t phi[4], plo[4];
            #pragma unroll
            for (int s = 0; s < 8; ++s) {
                const int k2 = s >> 2, p = s & 3;
                const int cb = s & 1, nb = cb ^ 1;
                if (p == 0) {
                    float e0 = ex2f(acc1[2*k2][0]);
                    float e1 = ex2f(acc1[2*k2][1]);
                    float e2 = ex2f(acc1[2*k2][2]);
                    float e3 = ex2f(acc1[2*k2][3]);
                    split_pack(e0, e1, phi[0], plo[0]);
                    split_pack(e2, e3, phi[1], plo[1]);
                    float f0 = ex2f(acc1[2*k2+1][0]);
                    float f1 = ex2f(acc1[2*k2+1][1]);
                    float f2 = ex2f(acc1[2*k2+1][2]);
                    float f3 = ex2f(acc1[2*k2+1][3]);
                    split_pack(f0, f1, phi[2], plo[2]);
                    split_pack(f2, f3, phi[3], plo[3]);
                }
                if (s < 7) {
                    const int s2 = s + 1;
                    uint32_t bb = bV + cur +
                        (uint32_t)((s2 >> 2) * 16 * PITCH + (s2 & 3) * 32);
                    LDMX4T(Vh[nb], bb);
                    LDMX4T(Vl[nb], bb + KBUF);
                }
                MMA(acc2[2*p],   phi, Vh[cb]);
                MMA(acc2[2*p],   phi, Vl[cb]);
                MMA(acc2[2*p],   plo, Vh[cb]);
                MMA(acc2[2*p+1], phi, Vh[cb] + 2);
                MMA(acc2[2*p+1], phi, Vl[cb] + 2);
                MMA(acc2[2*p+1], plo, Vh[cb] + 2);
            }
        }

        // ---- wait + barrier every 3 tiles (t % 3 == 2) ----
        if (t - (t / 3) * 3 == 2) {
            CP_WAIT0();
            __syncthreads();
        }

        if (++stage == NSTG) stage = 0;
    }

    // ---- split-K reduction: g==1 -> smem, g==0 adds and stores ----
    __syncthreads();
    float* red = (float*)smem;
    if (g == 1) {
        #pragma unroll
        for (int ni = 0; ni < 8; ++ni) {
            int r = m * 16 + (lane >> 2);
            int c = ni * 8 + (lane & 3) * 2;
            *(float2*)&red[r * RED_PITCH + c] =
                make_float2(acc2[ni][0], acc2[ni][1]);
            *(float2*)&red[(r + 8) * RED_PITCH + c] =
                make_float2(acc2[ni][2], acc2[ni][3]);
        }
    }
    __syncthreads();
    if (g == 0) {
        #pragma unroll
        for (int ni = 0; ni < 8; ++ni) {
            int r = m * 16 + (lane >> 2);
            int c = ni * 8 + (lane & 3) * 2;
            float2 p0 = *(const float2*)&red[r * RED_PITCH + c];
            float2 p1 = *(const float2*)&red[(r + 8) * RED_PITCH + c];
            *(float2*)&Og[(size_t)r * DD + c] =
                make_float2(acc2[ni][0] + p0.x, acc2[ni][1] + p0.y);
            *(float2*)&Og[(size_t)(r + 8) * DD + c] =
                make_float2(acc2[ni][2] + p1.x, acc2[ni][3] + p1.y);
        }
    }
}

extern "C" void kernel_launch(void* const* d_in, const int* in_sizes, int n_in,
                              void* d_out, int out_size)
{
    const float* q = (const float*)d_in[0];
    const float* k = (const float*)d_in[1];
    const float* v = (const float*)d_in[2];
    float* out = (float*)d_out;
    (void)in_sizes; (void)n_in; (void)out_size;

    split_kv_kernel<<<512, 256>>>(k, v);

    cudaFuncSetAttribute(fa_fa17_kernel,
                         cudaFuncAttributeMaxDynamicSharedMemorySize, SM_TOTAL);
    dim3 grid(S_LEN / TQ, B_SZ);   // 32 x 4 = 128 CTAs, one wave
    fa_fa17_kernel<<<grid, NTH, SM_TOTAL>>>(q, out);
}